// round 14
// baseline (speedup 1.0000x reference)
#include <cuda_runtime.h>
#include <cuda_bf16.h>
#include <mma.h>
#include <math.h>
#include <stdint.h>

using namespace nvcuda;

// ---------------------------------------------------------------------------
// GRU (Keras reset_after=True):  B=32, T=1024, D=1024, H=1024
//  Phase 1: x_proj = input @ kernel   (split kernels + WMMA bf16 3x-split)
//  Phase 2: recurrence — R13 persistent kernel (6.9us/step) with:
//    (1) out-store deferred past the barrier fence (only g_hbf in fence window)
//    (2) split accumulators (shorter dependent HMMA chain)
//    (3) 4-chunk staged h broadcast (earlier gemm start)
// NOTE: harness emits compute_103 PTX -> NO tcgen05/'a'-suffix features.
// ---------------------------------------------------------------------------

#define BB 32
#define TT 1024
#define DD 1024
#define HH 1024
#define H3 3072
#define BT (BB * TT)

// scratch (device globals only -- no allocation allowed)
__device__ float         g_xproj[(size_t)BT * H3];           // 402 MB (raw x@W)
__device__ __nv_bfloat16 g_Ah[(size_t)BT * DD];              // 64 MB
__device__ __nv_bfloat16 g_Al[(size_t)BT * DD];              // 64 MB
__device__ __nv_bfloat16 g_Bh[(size_t)H3 * DD];              // 6 MB  (kernel^T hi)
__device__ __nv_bfloat16 g_Bl[(size_t)H3 * DD];              // 6 MB  (kernel^T lo)
// per-step h in bf16 hi/lo, DOUBLE-BUFFERED by t parity; each: [k=1024][b=32]
__device__ __nv_bfloat16 g_hbf[2][2 * HH * BB];              // 2 x 128 KB

#define NCTA 128
__device__ unsigned g_arrive = 0;           // R6 barrier counter (atomic-hot)
__device__ unsigned g_exit   = 0;

// ------------------------------ helpers ------------------------------------
__device__ __forceinline__ unsigned smaddr(const void* p) {
    return (unsigned)__cvta_generic_to_shared(p);
}
__device__ __forceinline__ void cp_async16(uint32_t saddr, const void* g) {
    asm volatile("cp.async.cg.shared.global [%0], [%1], 16;" :: "r"(saddr), "l"(g)
                 : "memory");
}
#define CP_COMMIT() asm volatile("cp.async.commit_group;" ::: "memory")
#define CP_WAIT_1() asm volatile("cp.async.wait_group 1;" ::: "memory")
#define CP_WAIT_0() asm volatile("cp.async.wait_group 0;" ::: "memory")

#define LDSM_X4_T(r0, r1, r2, r3, addr) \
    asm volatile("ldmatrix.sync.aligned.m8n8.x4.trans.shared.b16 {%0,%1,%2,%3}, [%4];" \
                 : "=r"(r0), "=r"(r1), "=r"(r2), "=r"(r3) : "r"(addr))
#define LDSM_X2_T(r0, r1, addr) \
    asm volatile("ldmatrix.sync.aligned.m8n8.x2.trans.shared.b16 {%0,%1}, [%2];" \
                 : "=r"(r0), "=r"(r1) : "r"(addr))
#define MMA_BF16(d, a, b) \
    asm volatile("mma.sync.aligned.m16n8k16.row.col.f32.bf16.bf16.f32 " \
                 "{%0,%1,%2,%3}, {%4,%5,%6,%7}, {%8,%9}, {%0,%1,%2,%3};" \
                 : "+f"((d)[0]), "+f"((d)[1]), "+f"((d)[2]), "+f"((d)[3]) \
                 : "r"((a)[0]), "r"((a)[1]), "r"((a)[2]), "r"((a)[3]), \
                   "r"((b)[0]), "r"((b)[1]))

// single shared dynamic-smem symbol (same type in every kernel)
extern __shared__ char dynsmem[];

// ---------------------------------------------------------------------------
// Split kernels
// ---------------------------------------------------------------------------
__global__ void __launch_bounds__(256) splitA_kernel(const float* __restrict__ A) {
    size_t i = (size_t)blockIdx.x * 256 + threadIdx.x;  // float4 index
    float4 v = ((const float4*)A)[i];
    __nv_bfloat16 h0 = __float2bfloat16(v.x);
    __nv_bfloat16 h1 = __float2bfloat16(v.y);
    __nv_bfloat16 h2 = __float2bfloat16(v.z);
    __nv_bfloat16 h3 = __float2bfloat16(v.w);
    __nv_bfloat16 l0 = __float2bfloat16(v.x - __bfloat162float(h0));
    __nv_bfloat16 l1 = __float2bfloat16(v.y - __bfloat162float(h1));
    __nv_bfloat16 l2 = __float2bfloat16(v.z - __bfloat162float(h2));
    __nv_bfloat16 l3 = __float2bfloat16(v.w - __bfloat162float(h3));
    ((__nv_bfloat162*)g_Ah)[2 * i]     = __nv_bfloat162(h0, h1);
    ((__nv_bfloat162*)g_Ah)[2 * i + 1] = __nv_bfloat162(h2, h3);
    ((__nv_bfloat162*)g_Al)[2 * i]     = __nv_bfloat162(l0, l1);
    ((__nv_bfloat162*)g_Al)[2 * i + 1] = __nv_bfloat162(l2, l3);
}

// W[k][n] -> Bh/Bl[n][k] (transpose + split)
__global__ void __launch_bounds__(256) splitW_kernel(const float* __restrict__ W) {
    __shared__ float tile[32][33];
    const int n0 = blockIdx.x * 32;
    const int k0 = blockIdx.y * 32;
    const int tx = threadIdx.x & 31;
    const int ty = threadIdx.x >> 5;  // 0..7
#pragma unroll
    for (int r = 0; r < 32; r += 8)
        tile[ty + r][tx] = W[(size_t)(k0 + ty + r) * H3 + n0 + tx];
    __syncthreads();
#pragma unroll
    for (int r = 0; r < 32; r += 8) {
        int n = n0 + ty + r;
        float v = tile[tx][ty + r];
        __nv_bfloat16 hi = __float2bfloat16(v);
        __nv_bfloat16 lo = __float2bfloat16(v - __bfloat162float(hi));
        g_Bh[(size_t)n * DD + k0 + tx] = hi;
        g_Bl[(size_t)n * DD + k0 + tx] = lo;
    }
}

// ---------------------------------------------------------------------------
// x_proj WMMA kernel: C[128,128] per CTA, 256 thr (8 warps, warp tile 32x64).
// ---------------------------------------------------------------------------
#define X_BK 32
#define X_LDT 40
#define X_MAT_ELEMS (128 * X_LDT)
#define X_STAGE_ELEMS (4 * X_MAT_ELEMS)
#define X_SMEM_BYTES (2 * X_STAGE_ELEMS * 2)

typedef wmma::fragment<wmma::matrix_a, 16, 16, 16, __nv_bfloat16, wmma::row_major> AFrag;
typedef wmma::fragment<wmma::matrix_b, 16, 16, 16, __nv_bfloat16, wmma::col_major> BFrag;
typedef wmma::fragment<wmma::accumulator, 16, 16, 16, float> CFrag;

__device__ __forceinline__ void xp_load_stage(__nv_bfloat16* base, int m0, int n0,
                                              int k0, int tid) {
    const __nv_bfloat16* gsrc[4] = {
        g_Ah + (size_t)m0 * DD + k0,
        g_Al + (size_t)m0 * DD + k0,
        g_Bh + (size_t)n0 * DD + k0,
        g_Bl + (size_t)n0 * DD + k0,
    };
#pragma unroll
    for (int it = 0; it < 8; it++) {
        int idx = it * 256 + tid;
        int q = idx >> 9;
        int r = (idx >> 2) & 127;
        int c = idx & 3;
        cp_async16(smaddr(base + q * X_MAT_ELEMS + r * X_LDT + c * 8),
                   gsrc[q] + (size_t)r * DD + c * 8);
    }
}

__global__ void __launch_bounds__(256) xproj_wmma_kernel() {
    __nv_bfloat16* sm = (__nv_bfloat16*)dynsmem;
    const int tid  = threadIdx.x;
    const int warp = tid >> 5;
    const int m0 = (blockIdx.x / (H3 / 128)) * 128;
    const int n0 = (blockIdx.x % (H3 / 128)) * 128;
    const int wm = warp & 3;
    const int wn = warp >> 2;

    CFrag acc[2][4];
#pragma unroll
    for (int i = 0; i < 2; i++)
#pragma unroll
        for (int j = 0; j < 4; j++) wmma::fill_fragment(acc[i][j], 0.0f);

    xp_load_stage(sm, m0, n0, 0, tid);
    CP_COMMIT();
    xp_load_stage(sm + X_STAGE_ELEMS, m0, n0, X_BK, tid);
    CP_COMMIT();

    for (int ss = 0; ss < 32; ss++) {
        const int s = ss & 1;
        if (ss == 31) { CP_WAIT_0(); } else { CP_WAIT_1(); }
        __syncthreads();

        const __nv_bfloat16* base = sm + s * X_STAGE_ELEMS;
        const __nv_bfloat16* sAh = base;
        const __nv_bfloat16* sAl = base + X_MAT_ELEMS;
        const __nv_bfloat16* sBh = base + 2 * X_MAT_ELEMS;
        const __nv_bfloat16* sBl = base + 3 * X_MAT_ELEMS;

#pragma unroll
        for (int kk = 0; kk < 2; kk++) {
            const int ko = kk * 16;
            AFrag ah[2], al[2];
            BFrag bh[4], bl[4];
#pragma unroll
            for (int i = 0; i < 2; i++) {
                wmma::load_matrix_sync(ah[i], sAh + (wm * 32 + i * 16) * X_LDT + ko, X_LDT);
                wmma::load_matrix_sync(al[i], sAl + (wm * 32 + i * 16) * X_LDT + ko, X_LDT);
            }
#pragma unroll
            for (int j = 0; j < 4; j++) {
                wmma::load_matrix_sync(bh[j], sBh + (wn * 64 + j * 16) * X_LDT + ko, X_LDT);
                wmma::load_matrix_sync(bl[j], sBl + (wn * 64 + j * 16) * X_LDT + ko, X_LDT);
            }
#pragma unroll
            for (int i = 0; i < 2; i++)
#pragma unroll
                for (int j = 0; j < 4; j++) {
                    wmma::mma_sync(acc[i][j], ah[i], bh[j], acc[i][j]);
                    wmma::mma_sync(acc[i][j], ah[i], bl[j], acc[i][j]);
                    wmma::mma_sync(acc[i][j], al[i], bh[j], acc[i][j]);
                }
        }

        __syncthreads();
        if (ss + 2 < 32) {
            xp_load_stage(sm + s * X_STAGE_ELEMS, m0, n0, (ss + 2) * X_BK, tid);
            CP_COMMIT();
        }
    }

#pragma unroll
    for (int i = 0; i < 2; i++)
#pragma unroll
        for (int j = 0; j < 4; j++) {
            float* p = g_xproj + (size_t)(m0 + wm * 32 + i * 16) * H3 +
                       n0 + wn * 64 + j * 16;
            wmma::store_matrix_sync(p, acc[i][j], H3, wmma::mem_row_major);
        }
}

// ---------------------------------------------------------------------------
// Kernel B: persistent GRU recurrence, tensor-core GEMM.
// 128 CTAs x 512 threads. CTA owns 24 rec cols (8 j-units x {z,r,h}).
// smem: A (h hi|lo, swizzled) 128 KB; U hi/lo bf16 [k][24] 96 KB.
// 12 mma warps: nt = w%3 (8-col tile), ks = w/3 (64-k piece per chunk).
// Staging: FOUR cp.async commit groups (256 k each); gemm piece p overlaps
// chunk p+1 staging. Split accumulators shorten the dependent HMMA chain.
// out-store deferred to next step (fence window holds only g_hbf).
// Barrier: R6 same-address atomic + single-thread poll.
// ---------------------------------------------------------------------------
#define JB 8
#define NCOL 24
#define SM_A_BYTES (HH * 128)                 // 131072: [k][128B] hi|lo chunks
#define SM_B_BYTES (HH * NCOL * 2)            // 49152 per split
#define SMEM_BYTES (SM_A_BYTES + 2 * SM_B_BYTES)   // 229376
#define PSTRIDE 26

__global__ void __launch_bounds__(512, 1) gru_kernel(
    const float* __restrict__ U,    // [H, 3H]
    const float* __restrict__ bias, // [2, 3H]
    float* __restrict__ out,        // [B, T, H]
    float* __restrict__ hlast,
    int write_hlast
) {
    char* smA = dynsmem;                                // 128 KB
    __nv_bfloat16* smBh = (__nv_bfloat16*)(dynsmem + SM_A_BYTES);
    __nv_bfloat16* smBl = (__nv_bfloat16*)(dynsmem + SM_A_BYTES + SM_B_BYTES);
    float* smP = (float*)dynsmem;                       // partials alias A

    const int tid  = threadIdx.x;
    const int bid  = blockIdx.x;
    const int j0   = bid * JB;
    const int lane = tid & 31;
    const int warp = tid >> 5;          // 0..15

    // ---- one-time U slice load + split to bf16 hi/lo ----
    for (int idx = tid; idx < HH * NCOL; idx += 512) {
        int k = idx / NCOL;
        int n = idx % NCOL;
        int g = n >> 3;
        int jj = n & 7;
        float v = __ldg(&U[(size_t)k * H3 + g * HH + j0 + jj]);
        __nv_bfloat16 hi = __float2bfloat16(v);
        smBh[idx] = hi;
        smBl[idx] = __float2bfloat16(v - __bfloat162float(hi));
    }

    // ---- gate identity (tid < 256): thread = (b = tid&31, jj = (tid>>5)&7) ----
    const int gb   = tid & 31;
    const int gjj  = (tid >> 5) & 7;
    const int jloc = j0 + gjj;
    const float bz = __ldg(&bias[jloc])      + __ldg(&bias[H3 + jloc]);
    const float br = __ldg(&bias[HH + jloc]) + __ldg(&bias[H3 + HH + jloc]);
    const float binh = __ldg(&bias[2 * HH + jloc]);
    const float brh  = __ldg(&bias[H3 + 2 * HH + jloc]);

    // ---- mma identity: 12 warps -> nt (n 8-col tile), ks (64-k piece) ----
    const int nt = warp % 3;
    const int ks = warp / 3;            // 0..3
    const unsigned aBase = smaddr(smA);
    const unsigned bhBase = smaddr(smBh);
    const unsigned blBase = smaddr(smBl);
    const unsigned pBase = smaddr(smP);

    // per-lane constant addressing for ldmatrix
    const int laneoffA = (lane & 7) + ((lane & 16) ? 8 : 0);  // k row offset
    const int hb = (lane >> 3) & 1;                            // chunk +1
    const unsigned swzA = (unsigned)((lane & 7) << 4);         // xor term (k&7)*16
    const int laneoffB = (lane & 7) + ((lane & 8) ? 8 : 0);

    float hp = 0.0f;     // previous h for this gate thread (register-resident)
    float hout = 0.0f;   // deferred out value (stored next iteration)

    for (int t = 0; t < TT; t++) {
        if (t > 0) {
            // ---- stage h(t-1) in FOUR commit groups (256 k each) ----
            const __nv_bfloat16* hsrc = g_hbf[(t + 1) & 1];
#pragma unroll
            for (int p = 0; p < 4; p++) {
#pragma unroll
                for (int i = p * 4; i < p * 4 + 4; i++) {
                    int idx = tid + i * 512;
                    int k = idx >> 3;
                    int c = idx & 7;
                    const __nv_bfloat16* src =
                        hsrc + ((c & 4) ? (HH * BB) : 0) + k * BB + (c & 3) * 8;
                    unsigned dst = aBase + (unsigned)(k * 128) +
                                   (unsigned)(((c * 16) ^ ((k & 7) * 16)));
                    cp_async16(dst, src);
                }
                CP_COMMIT();
            }
            // deferred out store for step t-1 (overlaps staging; NOT in fence)
            if (tid < 256)
                __stcg(&out[((size_t)gb * TT + (t - 1)) * HH + jloc], hout);
        }

        // prefetch x_proj for gate phase (hidden behind staging + gemm)
        float xz = 0.f, xr = 0.f, xh = 0.f;
        if (tid < 256) {
            const size_t xrow = ((size_t)gb * TT + t) * H3;
            xz = __ldg(&g_xproj[xrow + jloc]);
            xr = __ldg(&g_xproj[xrow + HH + jloc]);
            xh = __ldg(&g_xproj[xrow + 2 * HH + jloc]);
        }

        if (t > 0) {
            float acc0a[4] = {0.f, 0.f, 0.f, 0.f};
            float acc0b[4] = {0.f, 0.f, 0.f, 0.f};
            float acc1a[4] = {0.f, 0.f, 0.f, 0.f};
            float acc1b[4] = {0.f, 0.f, 0.f, 0.f};

#pragma unroll
            for (int p = 0; p < 4; p++) {
                if (p == 0)      asm volatile("cp.async.wait_group 3;" ::: "memory");
                else if (p == 1) asm volatile("cp.async.wait_group 2;" ::: "memory");
                else if (p == 2) asm volatile("cp.async.wait_group 1;" ::: "memory");
                else             asm volatile("cp.async.wait_group 0;" ::: "memory");
                __syncthreads();

                if (warp < 12) {
                    const int kbase = p * 256 + ks * 64;
                    unsigned rowA = aBase + (unsigned)((kbase + laneoffA) * 128);
                    unsigned aH0 = rowA + ((unsigned)((0 + hb) * 16) ^ swzA);
                    unsigned aH1 = rowA + ((unsigned)((2 + hb) * 16) ^ swzA);
                    unsigned aL0 = rowA + ((unsigned)((4 + hb) * 16) ^ swzA);
                    unsigned aL1 = rowA + ((unsigned)((6 + hb) * 16) ^ swzA);
                    unsigned bH = bhBase + (unsigned)((kbase + laneoffB) * (NCOL * 2) + nt * 16);
                    unsigned bL = blBase + (unsigned)((kbase + laneoffB) * (NCOL * 2) + nt * 16);

#pragma unroll
                    for (int kt = 0; kt < 4; kt++) {
                        uint32_t ah0[4], ah1[4], al0[4], al1[4], fbh[2], fbl[2];
                        LDSM_X4_T(ah0[0], ah0[1], ah0[2], ah0[3], aH0);
                        LDSM_X4_T(ah1[0], ah1[1], ah1[2], ah1[3], aH1);
                        LDSM_X4_T(al0[0], al0[1], al0[2], al0[3], aL0);
                        LDSM_X4_T(al1[0], al1[1], al1[2], al1[3], aL1);
                        LDSM_X2_T(fbh[0], fbh[1], bH);
                        LDSM_X2_T(fbl[0], fbl[1], bL);
                        MMA_BF16(acc0a, ah0, fbh);
                        MMA_BF16(acc0b, ah0, fbl);
                        MMA_BF16(acc0b, al0, fbh);
                        MMA_BF16(acc1a, ah1, fbh);
                        MMA_BF16(acc1b, ah1, fbl);
                        MMA_BF16(acc1b, al1, fbh);
                        aH0 += 16 * 128; aH1 += 16 * 128;
                        aL0 += 16 * 128; aL1 += 16 * 128;
                        bH += 16 * (NCOL * 2); bL += 16 * (NCOL * 2);
                    }
                }
            }

            __syncthreads();   // all A reads complete before partials alias A

            if (warp < 12) {
                const int r = lane >> 2;
                const int c = (lane & 3) * 2;
                const int n = nt * 8 + c;
                float s0 = acc0a[0] + acc0b[0], s1 = acc0a[1] + acc0b[1];
                float s2 = acc0a[2] + acc0b[2], s3 = acc0a[3] + acc0b[3];
                float s4 = acc1a[0] + acc1b[0], s5 = acc1a[1] + acc1b[1];
                float s6 = acc1a[2] + acc1b[2], s7 = acc1a[3] + acc1b[3];
                unsigned p0 = pBase + (unsigned)(((ks * 32 + r) * PSTRIDE + n) * 4);
                unsigned p1 = pBase + (unsigned)(((ks * 32 + r + 8) * PSTRIDE + n) * 4);
                unsigned p2 = pBase + (unsigned)(((ks * 32 + r + 16) * PSTRIDE + n) * 4);
                unsigned p3 = pBase + (unsigned)(((ks * 32 + r + 24) * PSTRIDE + n) * 4);
                asm volatile("st.shared.v2.f32 [%0], {%1, %2};" :: "r"(p0), "f"(s0), "f"(s1) : "memory");
                asm volatile("st.shared.v2.f32 [%0], {%1, %2};" :: "r"(p1), "f"(s2), "f"(s3) : "memory");
                asm volatile("st.shared.v2.f32 [%0], {%1, %2};" :: "r"(p2), "f"(s4), "f"(s5) : "memory");
                asm volatile("st.shared.v2.f32 [%0], {%1, %2};" :: "r"(p3), "f"(s6), "f"(s7) : "memory");
            }
            __syncthreads();
        }

        // ---- gate math (tid < 256) ----
        if (tid < 256) {
            float rz = 0.f, rr = 0.f, rh = 0.f;
            if (t > 0) {
#pragma unroll
                for (int q = 0; q < 4; q++) {
                    const float* pp = smP + (q * 32 + gb) * PSTRIDE;
                    rz += pp[gjj];
                    rr += pp[8 + gjj];
                    rh += pp[16 + gjj];
                }
            }
            const float z   = 1.0f / (1.0f + expf(-(xz + rz + bz)));
            const float r   = 1.0f / (1.0f + expf(-(xr + rr + br)));
            const float hhv = tanhf(xh + binh + r * (rh + brh));
            const float hn  = z * hp + (1.0f - z) * hhv;
            hp = hn;
            hout = hn;                       // deferred DRAM store
            // emit bf16 hi/lo into parity buffer for next step's GEMM
            __nv_bfloat16 hi = __float2bfloat16(hn);
            __nv_bfloat16 lo = __float2bfloat16(hn - __bfloat162float(hi));
            __nv_bfloat16* hdst = &g_hbf[t & 1][0];
            hdst[jloc * BB + gb] = hi;
            hdst[HH * BB + jloc * BB + gb] = lo;
        }

        // ---- R6 grid barrier (same-address atomic, single poll thread) ----
        if (t < TT - 1) {
            __syncthreads();                       // CTA's g_hbf writes done
            if (tid == 0) {
                __threadfence();                   // drains only g_hbf (512 B)
                atomicAdd(&g_arrive, 1u);
                const unsigned target = (unsigned)(t + 1) * NCTA;
                while (*(volatile unsigned*)&g_arrive < target) { }
                __threadfence();
            }
            __syncthreads();
        }
    }

    // ---- final deferred stores ----
    if (tid < 256) {
        __stcg(&out[((size_t)gb * TT + (TT - 1)) * HH + jloc], hout);
        if (write_hlast)
            __stcg(&hlast[(size_t)gb * HH + jloc], hout);
    }

    // ---- reset barrier state (last exiting CTA) for graph replay ----
    __syncthreads();
    if (tid == 0) {
        __threadfence();
        unsigned r = atomicAdd(&g_exit, 1u);
        if (r == NCTA - 1) {
            *(volatile unsigned*)&g_arrive = 0;
            __threadfence();
            *(volatile unsigned*)&g_exit = 0;
            __threadfence();
        }
    }
}

// ---------------------------------------------------------------------------
extern "C" void kernel_launch(void* const* d_in, const int* in_sizes, int n_in,
                              void* d_out, int out_size) {
    const float* input = (const float*)d_in[0];   // [B,T,D]
    const float* kern  = (const float*)d_in[1];   // [D,3H]
    const float* U     = (const float*)d_in[2];   // [H,3H]
    const float* bias  = (const float*)d_in[3];   // [2,3H]

    float* out = (float*)d_out;
    const size_t out_elems = (size_t)BB * TT * HH;
    int write_hlast = (out_size >= (int)(out_elems + BB * HH)) ? 1 : 0;
    float* hlast = out + out_elems;

    static int attr_set = 0;
    if (!attr_set) {
        cudaFuncSetAttribute(gru_kernel,
                             cudaFuncAttributeMaxDynamicSharedMemorySize, SMEM_BYTES);
        cudaFuncSetAttribute(xproj_wmma_kernel,
                             cudaFuncAttributeMaxDynamicSharedMemorySize, X_SMEM_BYTES);
        attr_set = 1;
    }

    // Phase 1a: split inputs
    splitA_kernel<<<(BT * DD / 4 + 255) / 256, 256>>>(input);
    splitW_kernel<<<dim3(H3 / 32, DD / 32), 256>>>(kern);

    // Phase 1b: x_proj via WMMA bf16 (3xBF16 split)
    xproj_wmma_kernel<<<(BT / 128) * (H3 / 128), 256, X_SMEM_BYTES>>>();

    // Phase 2: persistent recurrence (tensor-core h@U)
    gru_kernel<<<NCTA, 512, SMEM_BYTES>>>(U, bias, out, hlast, write_hlast);
}

// round 15
// speedup vs baseline: 1.5242x; 1.5242x over previous
#include <cuda_runtime.h>
#include <cuda_bf16.h>
#include <mma.h>
#include <math.h>
#include <stdint.h>

using namespace nvcuda;

// ---------------------------------------------------------------------------
// GRU (Keras reset_after=True):  B=32, T=1024, D=1024, H=1024
//  Phase 1: x_proj = input @ kernel   (split kernels + WMMA bf16 3x-split)
//  Phase 2: recurrence — R13 persistent kernel (6.9us/step, 2-chunk staging)
//    + deferred out-store (fence window holds only g_hbf)
//    + split accumulators (shorter dependent HMMA chain)
//    (R14's 4-chunk staging REVERTED — convicted as the regression.)
// NOTE: harness emits compute_103 PTX -> NO tcgen05/'a'-suffix features.
// ---------------------------------------------------------------------------

#define BB 32
#define TT 1024
#define DD 1024
#define HH 1024
#define H3 3072
#define BT (BB * TT)

// scratch (device globals only -- no allocation allowed)
__device__ float         g_xproj[(size_t)BT * H3];           // 402 MB (raw x@W)
__device__ __nv_bfloat16 g_Ah[(size_t)BT * DD];              // 64 MB
__device__ __nv_bfloat16 g_Al[(size_t)BT * DD];              // 64 MB
__device__ __nv_bfloat16 g_Bh[(size_t)H3 * DD];              // 6 MB  (kernel^T hi)
__device__ __nv_bfloat16 g_Bl[(size_t)H3 * DD];              // 6 MB  (kernel^T lo)
// per-step h in bf16 hi/lo, DOUBLE-BUFFERED by t parity; each: [k=1024][b=32]
__device__ __nv_bfloat16 g_hbf[2][2 * HH * BB];              // 2 x 128 KB

#define NCTA 128
__device__ unsigned g_arrive = 0;           // R6 barrier counter (atomic-hot)
__device__ unsigned g_exit   = 0;

// ------------------------------ helpers ------------------------------------
__device__ __forceinline__ unsigned smaddr(const void* p) {
    return (unsigned)__cvta_generic_to_shared(p);
}
__device__ __forceinline__ void cp_async16(uint32_t saddr, const void* g) {
    asm volatile("cp.async.cg.shared.global [%0], [%1], 16;" :: "r"(saddr), "l"(g)
                 : "memory");
}
#define CP_COMMIT() asm volatile("cp.async.commit_group;" ::: "memory")
#define CP_WAIT_1() asm volatile("cp.async.wait_group 1;" ::: "memory")
#define CP_WAIT_0() asm volatile("cp.async.wait_group 0;" ::: "memory")

#define LDSM_X4_T(r0, r1, r2, r3, addr) \
    asm volatile("ldmatrix.sync.aligned.m8n8.x4.trans.shared.b16 {%0,%1,%2,%3}, [%4];" \
                 : "=r"(r0), "=r"(r1), "=r"(r2), "=r"(r3) : "r"(addr))
#define LDSM_X2_T(r0, r1, addr) \
    asm volatile("ldmatrix.sync.aligned.m8n8.x2.trans.shared.b16 {%0,%1}, [%2];" \
                 : "=r"(r0), "=r"(r1) : "r"(addr))
#define MMA_BF16(d, a, b) \
    asm volatile("mma.sync.aligned.m16n8k16.row.col.f32.bf16.bf16.f32 " \
                 "{%0,%1,%2,%3}, {%4,%5,%6,%7}, {%8,%9}, {%0,%1,%2,%3};" \
                 : "+f"((d)[0]), "+f"((d)[1]), "+f"((d)[2]), "+f"((d)[3]) \
                 : "r"((a)[0]), "r"((a)[1]), "r"((a)[2]), "r"((a)[3]), \
                   "r"((b)[0]), "r"((b)[1]))

// single shared dynamic-smem symbol (same type in every kernel)
extern __shared__ char dynsmem[];

// ---------------------------------------------------------------------------
// Split kernels
// ---------------------------------------------------------------------------
__global__ void __launch_bounds__(256) splitA_kernel(const float* __restrict__ A) {
    size_t i = (size_t)blockIdx.x * 256 + threadIdx.x;  // float4 index
    float4 v = ((const float4*)A)[i];
    __nv_bfloat16 h0 = __float2bfloat16(v.x);
    __nv_bfloat16 h1 = __float2bfloat16(v.y);
    __nv_bfloat16 h2 = __float2bfloat16(v.z);
    __nv_bfloat16 h3 = __float2bfloat16(v.w);
    __nv_bfloat16 l0 = __float2bfloat16(v.x - __bfloat162float(h0));
    __nv_bfloat16 l1 = __float2bfloat16(v.y - __bfloat162float(h1));
    __nv_bfloat16 l2 = __float2bfloat16(v.z - __bfloat162float(h2));
    __nv_bfloat16 l3 = __float2bfloat16(v.w - __bfloat162float(h3));
    ((__nv_bfloat162*)g_Ah)[2 * i]     = __nv_bfloat162(h0, h1);
    ((__nv_bfloat162*)g_Ah)[2 * i + 1] = __nv_bfloat162(h2, h3);
    ((__nv_bfloat162*)g_Al)[2 * i]     = __nv_bfloat162(l0, l1);
    ((__nv_bfloat162*)g_Al)[2 * i + 1] = __nv_bfloat162(l2, l3);
}

// W[k][n] -> Bh/Bl[n][k] (transpose + split)
__global__ void __launch_bounds__(256) splitW_kernel(const float* __restrict__ W) {
    __shared__ float tile[32][33];
    const int n0 = blockIdx.x * 32;
    const int k0 = blockIdx.y * 32;
    const int tx = threadIdx.x & 31;
    const int ty = threadIdx.x >> 5;  // 0..7
#pragma unroll
    for (int r = 0; r < 32; r += 8)
        tile[ty + r][tx] = W[(size_t)(k0 + ty + r) * H3 + n0 + tx];
    __syncthreads();
#pragma unroll
    for (int r = 0; r < 32; r += 8) {
        int n = n0 + ty + r;
        float v = tile[tx][ty + r];
        __nv_bfloat16 hi = __float2bfloat16(v);
        __nv_bfloat16 lo = __float2bfloat16(v - __bfloat162float(hi));
        g_Bh[(size_t)n * DD + k0 + tx] = hi;
        g_Bl[(size_t)n * DD + k0 + tx] = lo;
    }
}

// ---------------------------------------------------------------------------
// x_proj WMMA kernel: C[128,128] per CTA, 256 thr (8 warps, warp tile 32x64).
// ---------------------------------------------------------------------------
#define X_BK 32
#define X_LDT 40
#define X_MAT_ELEMS (128 * X_LDT)
#define X_STAGE_ELEMS (4 * X_MAT_ELEMS)
#define X_SMEM_BYTES (2 * X_STAGE_ELEMS * 2)

typedef wmma::fragment<wmma::matrix_a, 16, 16, 16, __nv_bfloat16, wmma::row_major> AFrag;
typedef wmma::fragment<wmma::matrix_b, 16, 16, 16, __nv_bfloat16, wmma::col_major> BFrag;
typedef wmma::fragment<wmma::accumulator, 16, 16, 16, float> CFrag;

__device__ __forceinline__ void xp_load_stage(__nv_bfloat16* base, int m0, int n0,
                                              int k0, int tid) {
    const __nv_bfloat16* gsrc[4] = {
        g_Ah + (size_t)m0 * DD + k0,
        g_Al + (size_t)m0 * DD + k0,
        g_Bh + (size_t)n0 * DD + k0,
        g_Bl + (size_t)n0 * DD + k0,
    };
#pragma unroll
    for (int it = 0; it < 8; it++) {
        int idx = it * 256 + tid;
        int q = idx >> 9;
        int r = (idx >> 2) & 127;
        int c = idx & 3;
        cp_async16(smaddr(base + q * X_MAT_ELEMS + r * X_LDT + c * 8),
                   gsrc[q] + (size_t)r * DD + c * 8);
    }
}

__global__ void __launch_bounds__(256) xproj_wmma_kernel() {
    __nv_bfloat16* sm = (__nv_bfloat16*)dynsmem;
    const int tid  = threadIdx.x;
    const int warp = tid >> 5;
    const int m0 = (blockIdx.x / (H3 / 128)) * 128;
    const int n0 = (blockIdx.x % (H3 / 128)) * 128;
    const int wm = warp & 3;
    const int wn = warp >> 2;

    CFrag acc[2][4];
#pragma unroll
    for (int i = 0; i < 2; i++)
#pragma unroll
        for (int j = 0; j < 4; j++) wmma::fill_fragment(acc[i][j], 0.0f);

    xp_load_stage(sm, m0, n0, 0, tid);
    CP_COMMIT();
    xp_load_stage(sm + X_STAGE_ELEMS, m0, n0, X_BK, tid);
    CP_COMMIT();

    for (int ss = 0; ss < 32; ss++) {
        const int s = ss & 1;
        if (ss == 31) { CP_WAIT_0(); } else { CP_WAIT_1(); }
        __syncthreads();

        const __nv_bfloat16* base = sm + s * X_STAGE_ELEMS;
        const __nv_bfloat16* sAh = base;
        const __nv_bfloat16* sAl = base + X_MAT_ELEMS;
        const __nv_bfloat16* sBh = base + 2 * X_MAT_ELEMS;
        const __nv_bfloat16* sBl = base + 3 * X_MAT_ELEMS;

#pragma unroll
        for (int kk = 0; kk < 2; kk++) {
            const int ko = kk * 16;
            AFrag ah[2], al[2];
            BFrag bh[4], bl[4];
#pragma unroll
            for (int i = 0; i < 2; i++) {
                wmma::load_matrix_sync(ah[i], sAh + (wm * 32 + i * 16) * X_LDT + ko, X_LDT);
                wmma::load_matrix_sync(al[i], sAl + (wm * 32 + i * 16) * X_LDT + ko, X_LDT);
            }
#pragma unroll
            for (int j = 0; j < 4; j++) {
                wmma::load_matrix_sync(bh[j], sBh + (wn * 64 + j * 16) * X_LDT + ko, X_LDT);
                wmma::load_matrix_sync(bl[j], sBl + (wn * 64 + j * 16) * X_LDT + ko, X_LDT);
            }
#pragma unroll
            for (int i = 0; i < 2; i++)
#pragma unroll
                for (int j = 0; j < 4; j++) {
                    wmma::mma_sync(acc[i][j], ah[i], bh[j], acc[i][j]);
                    wmma::mma_sync(acc[i][j], ah[i], bl[j], acc[i][j]);
                    wmma::mma_sync(acc[i][j], al[i], bh[j], acc[i][j]);
                }
        }

        __syncthreads();
        if (ss + 2 < 32) {
            xp_load_stage(sm + s * X_STAGE_ELEMS, m0, n0, (ss + 2) * X_BK, tid);
            CP_COMMIT();
        }
    }

#pragma unroll
    for (int i = 0; i < 2; i++)
#pragma unroll
        for (int j = 0; j < 4; j++) {
            float* p = g_xproj + (size_t)(m0 + wm * 32 + i * 16) * H3 +
                       n0 + wn * 64 + j * 16;
            wmma::store_matrix_sync(p, acc[i][j], H3, wmma::mem_row_major);
        }
}

// ---------------------------------------------------------------------------
// Kernel B: persistent GRU recurrence, tensor-core GEMM (R13 structure).
// 128 CTAs x 512 threads. CTA owns 24 rec cols (8 j-units x {z,r,h}).
// smem: A (h hi|lo, swizzled) 128 KB; U hi/lo bf16 [k][24] 96 KB.
// 12 mma warps: nt = w%3 (8-col tile), ks = w/3 (128-k piece per chunk).
// Staging: TWO cp.async commit groups (512 k each); gemm piece0 overlaps
// chunk1 staging. Split accumulators; out-store deferred past the fence.
// Barrier: R6 same-address atomic + single-thread poll.
// ---------------------------------------------------------------------------
#define JB 8
#define NCOL 24
#define SM_A_BYTES (HH * 128)                 // 131072: [k][128B] hi|lo chunks
#define SM_B_BYTES (HH * NCOL * 2)            // 49152 per split
#define SMEM_BYTES (SM_A_BYTES + 2 * SM_B_BYTES)   // 229376
#define PSTRIDE 26

__global__ void __launch_bounds__(512, 1) gru_kernel(
    const float* __restrict__ U,    // [H, 3H]
    const float* __restrict__ bias, // [2, 3H]
    float* __restrict__ out,        // [B, T, H]
    float* __restrict__ hlast,
    int write_hlast
) {
    char* smA = dynsmem;                                // 128 KB
    __nv_bfloat16* smBh = (__nv_bfloat16*)(dynsmem + SM_A_BYTES);
    __nv_bfloat16* smBl = (__nv_bfloat16*)(dynsmem + SM_A_BYTES + SM_B_BYTES);
    float* smP = (float*)dynsmem;                       // partials alias A

    const int tid  = threadIdx.x;
    const int bid  = blockIdx.x;
    const int j0   = bid * JB;
    const int lane = tid & 31;
    const int warp = tid >> 5;          // 0..15

    // ---- one-time U slice load + split to bf16 hi/lo ----
    for (int idx = tid; idx < HH * NCOL; idx += 512) {
        int k = idx / NCOL;
        int n = idx % NCOL;
        int g = n >> 3;
        int jj = n & 7;
        float v = __ldg(&U[(size_t)k * H3 + g * HH + j0 + jj]);
        __nv_bfloat16 hi = __float2bfloat16(v);
        smBh[idx] = hi;
        smBl[idx] = __float2bfloat16(v - __bfloat162float(hi));
    }

    // ---- gate identity (tid < 256): thread = (b = tid&31, jj = (tid>>5)&7) ----
    const int gb   = tid & 31;
    const int gjj  = (tid >> 5) & 7;
    const int jloc = j0 + gjj;
    const float bz = __ldg(&bias[jloc])      + __ldg(&bias[H3 + jloc]);
    const float br = __ldg(&bias[HH + jloc]) + __ldg(&bias[H3 + HH + jloc]);
    const float binh = __ldg(&bias[2 * HH + jloc]);
    const float brh  = __ldg(&bias[H3 + 2 * HH + jloc]);

    // ---- mma identity: 12 warps -> nt (n 8-col tile), ks (k sub-slice) ----
    const int nt = warp % 3;
    const int ks = warp / 3;            // 0..3 -> 128-k piece within each chunk
    const unsigned aBase = smaddr(smA);
    const unsigned bhBase = smaddr(smBh);
    const unsigned blBase = smaddr(smBl);
    const unsigned pBase = smaddr(smP);

    // per-lane constant addressing for ldmatrix
    const int laneoffA = (lane & 7) + ((lane & 16) ? 8 : 0);  // k row offset
    const int hb = (lane >> 3) & 1;                            // chunk +1
    const unsigned swzA = (unsigned)((lane & 7) << 4);         // xor term (k&7)*16
    const int laneoffB = (lane & 7) + ((lane & 8) ? 8 : 0);

    float hp = 0.0f;     // previous h for this gate thread (register-resident)
    float hout = 0.0f;   // deferred out value (stored next iteration)

    for (int t = 0; t < TT; t++) {
        if (t > 0) {
            // ---- stage h(t-1) in TWO commit groups: chunk0 k<512, chunk1 k>=512 ----
            const __nv_bfloat16* hsrc = g_hbf[(t + 1) & 1];
#pragma unroll
            for (int i = 0; i < 8; i++) {           // chunk 0: k < 512
                int idx = tid + i * 512;
                int k = idx >> 3;
                int c = idx & 7;
                const __nv_bfloat16* src =
                    hsrc + ((c & 4) ? (HH * BB) : 0) + k * BB + (c & 3) * 8;
                unsigned dst = aBase + (unsigned)(k * 128) +
                               (unsigned)(((c * 16) ^ ((k & 7) * 16)));
                cp_async16(dst, src);
            }
            CP_COMMIT();
#pragma unroll
            for (int i = 8; i < 16; i++) {          // chunk 1: k >= 512
                int idx = tid + i * 512;
                int k = idx >> 3;
                int c = idx & 7;
                const __nv_bfloat16* src =
                    hsrc + ((c & 4) ? (HH * BB) : 0) + k * BB + (c & 3) * 8;
                unsigned dst = aBase + (unsigned)(k * 128) +
                               (unsigned)(((c * 16) ^ ((k & 7) * 16)));
                cp_async16(dst, src);
            }
            CP_COMMIT();
            // deferred out store for step t-1 (overlaps staging; NOT in fence)
            if (tid < 256)
                __stcg(&out[((size_t)gb * TT + (t - 1)) * HH + jloc], hout);
        }

        // prefetch x_proj for gate phase (hidden behind staging + gemm)
        float xz = 0.f, xr = 0.f, xh = 0.f;
        if (tid < 256) {
            const size_t xrow = ((size_t)gb * TT + t) * H3;
            xz = __ldg(&g_xproj[xrow + jloc]);
            xr = __ldg(&g_xproj[xrow + HH + jloc]);
            xh = __ldg(&g_xproj[xrow + 2 * HH + jloc]);
        }

        if (t > 0) {
            float acc0a[4] = {0.f, 0.f, 0.f, 0.f};
            float acc0b[4] = {0.f, 0.f, 0.f, 0.f};
            float acc1a[4] = {0.f, 0.f, 0.f, 0.f};
            float acc1b[4] = {0.f, 0.f, 0.f, 0.f};

#pragma unroll
            for (int p = 0; p < 2; p++) {
                if (p == 0) { CP_WAIT_1(); } else { CP_WAIT_0(); }
                __syncthreads();

                if (warp < 12) {
                    const int kbase = p * 512 + ks * 128;
                    unsigned rowA = aBase + (unsigned)((kbase + laneoffA) * 128);
                    unsigned aH0 = rowA + ((unsigned)((0 + hb) * 16) ^ swzA);
                    unsigned aH1 = rowA + ((unsigned)((2 + hb) * 16) ^ swzA);
                    unsigned aL0 = rowA + ((unsigned)((4 + hb) * 16) ^ swzA);
                    unsigned aL1 = rowA + ((unsigned)((6 + hb) * 16) ^ swzA);
                    unsigned bH = bhBase + (unsigned)((kbase + laneoffB) * (NCOL * 2) + nt * 16);
                    unsigned bL = blBase + (unsigned)((kbase + laneoffB) * (NCOL * 2) + nt * 16);

#pragma unroll 4
                    for (int kt = 0; kt < 8; kt++) {
                        uint32_t ah0[4], ah1[4], al0[4], al1[4], fbh[2], fbl[2];
                        LDSM_X4_T(ah0[0], ah0[1], ah0[2], ah0[3], aH0);
                        LDSM_X4_T(ah1[0], ah1[1], ah1[2], ah1[3], aH1);
                        LDSM_X4_T(al0[0], al0[1], al0[2], al0[3], aL0);
                        LDSM_X4_T(al1[0], al1[1], al1[2], al1[3], aL1);
                        LDSM_X2_T(fbh[0], fbh[1], bH);
                        LDSM_X2_T(fbl[0], fbl[1], bL);
                        MMA_BF16(acc0a, ah0, fbh);
                        MMA_BF16(acc0b, ah0, fbl);
                        MMA_BF16(acc0b, al0, fbh);
                        MMA_BF16(acc1a, ah1, fbh);
                        MMA_BF16(acc1b, ah1, fbl);
                        MMA_BF16(acc1b, al1, fbh);
                        aH0 += 16 * 128; aH1 += 16 * 128;
                        aL0 += 16 * 128; aL1 += 16 * 128;
                        bH += 16 * (NCOL * 2); bL += 16 * (NCOL * 2);
                    }
                }
            }

            __syncthreads();   // all A reads complete before partials alias A

            if (warp < 12) {
                const int r = lane >> 2;
                const int c = (lane & 3) * 2;
                const int n = nt * 8 + c;
                float s0 = acc0a[0] + acc0b[0], s1 = acc0a[1] + acc0b[1];
                float s2 = acc0a[2] + acc0b[2], s3 = acc0a[3] + acc0b[3];
                float s4 = acc1a[0] + acc1b[0], s5 = acc1a[1] + acc1b[1];
                float s6 = acc1a[2] + acc1b[2], s7 = acc1a[3] + acc1b[3];
                unsigned p0 = pBase + (unsigned)(((ks * 32 + r) * PSTRIDE + n) * 4);
                unsigned p1 = pBase + (unsigned)(((ks * 32 + r + 8) * PSTRIDE + n) * 4);
                unsigned p2 = pBase + (unsigned)(((ks * 32 + r + 16) * PSTRIDE + n) * 4);
                unsigned p3 = pBase + (unsigned)(((ks * 32 + r + 24) * PSTRIDE + n) * 4);
                asm volatile("st.shared.v2.f32 [%0], {%1, %2};" :: "r"(p0), "f"(s0), "f"(s1) : "memory");
                asm volatile("st.shared.v2.f32 [%0], {%1, %2};" :: "r"(p1), "f"(s2), "f"(s3) : "memory");
                asm volatile("st.shared.v2.f32 [%0], {%1, %2};" :: "r"(p2), "f"(s4), "f"(s5) : "memory");
                asm volatile("st.shared.v2.f32 [%0], {%1, %2};" :: "r"(p3), "f"(s6), "f"(s7) : "memory");
            }
            __syncthreads();
        }

        // ---- gate math (tid < 256) ----
        if (tid < 256) {
            float rz = 0.f, rr = 0.f, rh = 0.f;
            if (t > 0) {
#pragma unroll
                for (int q = 0; q < 4; q++) {
                    const float* pp = smP + (q * 32 + gb) * PSTRIDE;
                    rz += pp[gjj];
                    rr += pp[8 + gjj];
                    rh += pp[16 + gjj];
                }
            }
            const float z   = 1.0f / (1.0f + expf(-(xz + rz + bz)));
            const float r   = 1.0f / (1.0f + expf(-(xr + rr + br)));
            const float hhv = tanhf(xh + binh + r * (rh + brh));
            const float hn  = z * hp + (1.0f - z) * hhv;
            hp = hn;
            hout = hn;                       // deferred DRAM store
            // emit bf16 hi/lo into parity buffer for next step's GEMM
            __nv_bfloat16 hi = __float2bfloat16(hn);
            __nv_bfloat16 lo = __float2bfloat16(hn - __bfloat162float(hi));
            __nv_bfloat16* hdst = &g_hbf[t & 1][0];
            hdst[jloc * BB + gb] = hi;
            hdst[HH * BB + jloc * BB + gb] = lo;
        }

        // ---- R6 grid barrier (same-address atomic, single poll thread) ----
        if (t < TT - 1) {
            __syncthreads();                       // CTA's g_hbf writes done
            if (tid == 0) {
                __threadfence();                   // drains only g_hbf publish
                atomicAdd(&g_arrive, 1u);
                const unsigned target = (unsigned)(t + 1) * NCTA;
                while (*(volatile unsigned*)&g_arrive < target) { }
                __threadfence();
            }
            __syncthreads();
        }
    }

    // ---- final deferred stores ----
    if (tid < 256) {
        __stcg(&out[((size_t)gb * TT + (TT - 1)) * HH + jloc], hout);
        if (write_hlast)
            __stcg(&hlast[(size_t)gb * HH + jloc], hout);
    }

    // ---- reset barrier state (last exiting CTA) for graph replay ----
    __syncthreads();
    if (tid == 0) {
        __threadfence();
        unsigned r = atomicAdd(&g_exit, 1u);
        if (r == NCTA - 1) {
            *(volatile unsigned*)&g_arrive = 0;
            __threadfence();
            *(volatile unsigned*)&g_exit = 0;
            __threadfence();
        }
    }
}

// ---------------------------------------------------------------------------
extern "C" void kernel_launch(void* const* d_in, const int* in_sizes, int n_in,
                              void* d_out, int out_size) {
    const float* input = (const float*)d_in[0];   // [B,T,D]
    const float* kern  = (const float*)d_in[1];   // [D,3H]
    const float* U     = (const float*)d_in[2];   // [H,3H]
    const float* bias  = (const float*)d_in[3];   // [2,3H]

    float* out = (float*)d_out;
    const size_t out_elems = (size_t)BB * TT * HH;
    int write_hlast = (out_size >= (int)(out_elems + BB * HH)) ? 1 : 0;
    float* hlast = out + out_elems;

    static int attr_set = 0;
    if (!attr_set) {
        cudaFuncSetAttribute(gru_kernel,
                             cudaFuncAttributeMaxDynamicSharedMemorySize, SMEM_BYTES);
        cudaFuncSetAttribute(xproj_wmma_kernel,
                             cudaFuncAttributeMaxDynamicSharedMemorySize, X_SMEM_BYTES);
        attr_set = 1;
    }

    // Phase 1a: split inputs
    splitA_kernel<<<(BT * DD / 4 + 255) / 256, 256>>>(input);
    splitW_kernel<<<dim3(H3 / 32, DD / 32), 256>>>(kern);

    // Phase 1b: x_proj via WMMA bf16 (3xBF16 split)
    xproj_wmma_kernel<<<(BT / 128) * (H3 / 128), 256, X_SMEM_BYTES>>>();

    // Phase 2: persistent recurrence (tensor-core h@U)
    gru_kernel<<<NCTA, 512, SMEM_BYTES>>>(U, bias, out, hlast, write_hlast);
}